// round 8
// baseline (speedup 1.0000x reference)
#include <cuda_runtime.h>
#include <cuda_fp16.h>
#include <cstdint>
#include <math.h>

#define NNODE 512
#define CC 64
#define BT 2048
#define BTN 1048576
#define HN 67108864ULL
#define ALPHA 0.05f

// ---------------- device scratch (half operands, allocation-free) -------------
__device__ __half g_xh  [HN];          // x fp16 [bt][n][c]
__device__ __half g_hh  [HN];          // h [bt][n][f]
__device__ __half g_hTh [HN];          // h [bt][f][n]
__device__ __half g_h1fR[HN];          // hop1 fwd [n][f]
__device__ __half g_h1fT[HN];          // hop1 fwd [f][n]
__device__ __half g_h1rR[HN];
__device__ __half g_h1rT[HN];
__device__ __half g_h2f [HN];          // hop2 [n][f]
__device__ __half g_h2r [HN];
__device__ __half g_Afh [NNODE*NNODE]; // row-norm adj fp16
__device__ __half g_Arh [NNODE*NNODE];
__device__ __half g_WpadTh[7*128*64];  // [d][cout(interleaved 2j=f,2j+1=g)][cin]
__device__ float  g_bconv[128];
__device__ __half g_WfinTh[128*320];   // [cout][k]  cout<64 out, >=64 skip
__device__ float  g_bfin[128];

struct P {
    const float* x; const float* adj;
    const float* wf[4]; const float* bf[4];
    const float* wg[4]; const float* bg[4];
    const float* Wgf; const float* bgf;
    const float* Wgr; const float* bgr;
    const float* Ws;  const float* bs;
};

// ---------------- helpers -----------------------------------------------------
__device__ __forceinline__ void mma16(float* d, const uint32_t* a, const uint32_t* b) {
    asm volatile(
        "mma.sync.aligned.m16n8k16.row.col.f32.f16.f16.f32 "
        "{%0,%1,%2,%3}, {%4,%5,%6,%7}, {%8,%9}, {%0,%1,%2,%3};\n"
        : "+f"(d[0]), "+f"(d[1]), "+f"(d[2]), "+f"(d[3])
        : "r"(a[0]), "r"(a[1]), "r"(a[2]), "r"(a[3]), "r"(b[0]), "r"(b[1]));
}
__device__ __forceinline__ void cpa16(uint32_t dst, const void* src) {
    asm volatile("cp.async.cg.shared.global [%0], [%1], 16;" :: "r"(dst), "l"(src));
}
__device__ __forceinline__ void cp_commit() { asm volatile("cp.async.commit_group;"); }
template<int N> __device__ __forceinline__ void cp_wait() {
    asm volatile("cp.async.wait_group %0;" :: "n"(N) : "memory");
}
__device__ __forceinline__ uint32_t s2u(const void* p) {
    return (uint32_t)__cvta_generic_to_shared(p);
}
__device__ __forceinline__ uint32_t packh2(float a, float b) {
    __half2 h = __floats2half2_rn(a, b);
    return *reinterpret_cast<uint32_t*>(&h);
}
__device__ __forceinline__ float2 unph2(uint32_t u) {
    __half2 h = *reinterpret_cast<__half2*>(&u);
    return __half22float2(h);
}

// ---------------- prep: adjacencies (fp16) ------------------------------------
__global__ void prep_adj(const float* __restrict__ adj) {
    int n = blockIdx.x, tid = threadIdx.x;
    __shared__ float red[256];
    float s1 = 0.f, s2 = 0.f;
    for (int m = tid; m < NNODE; m += 256) {
        s1 += adj[n * NNODE + m];
        s2 += adj[m * NNODE + n];
    }
    red[tid] = s1; __syncthreads();
    for (int k = 128; k; k >>= 1) { if (tid < k) red[tid] += red[tid + k]; __syncthreads(); }
    float inv1 = 1.f / fmaxf(red[0] + 1.f, 1e-9f);
    __syncthreads();
    red[tid] = s2; __syncthreads();
    for (int k = 128; k; k >>= 1) { if (tid < k) red[tid] += red[tid + k]; __syncthreads(); }
    float inv2 = 1.f / fmaxf(red[0] + 1.f, 1e-9f);
    for (int m = tid; m < NNODE; m += 256) {
        g_Afh[n * NNODE + m] = __float2half_rn((adj[n * NNODE + m] + (m == n ? 1.f : 0.f)) * inv1);
        g_Arh[n * NNODE + m] = __float2half_rn((adj[m * NNODE + n] + (m == n ? 1.f : 0.f)) * inv2);
    }
}

// ---------------- prep: weights ------------------------------------------------
__global__ void prep_w(P p) {
    int idx = blockIdx.x * blockDim.x + threadIdx.x;
    const int KR[4] = {2, 3, 6, 7};
    if (idx < 57344) {                   // WpadTh[d][c][cin]
        int d = idx / 8192;
        int c = (idx >> 6) & 127;
        int cin = idx & 63;
        int j = c >> 1, gsel = c & 1;
        int i = j >> 4, r = j & 15;
        int k = KR[i], jj = k - 1 - d;
        float v = 0.f;
        if (jj >= 0) {
            const float* w = gsel ? p.wg[i] : p.wf[i];
            v = w[(jj * 64 + cin) * 16 + r];
        }
        g_WpadTh[idx] = __float2half_rn(v);
        return;
    }
    int i2 = idx - 57344;
    if (i2 < 128) {
        int j = i2 >> 1, gsel = i2 & 1;
        int i = j >> 4, r = j & 15;
        g_bconv[i2] = gsel ? p.bg[i][r] : p.bf[i][r];
        return;
    }
    int i3 = idx - 57472;
    if (i3 < 40960) {                    // WfinTh[c][k]
        int c = i3 / 320, k = i3 % 320;
        float v = 0.f;
        if (c < 64) {
            int s = k >> 6, kk = k & 63;
            if      (s == 0) v = p.Wgf[kk * 64 + c] + p.Wgr[kk * 64 + c];
            else if (s == 1) v = p.Wgf[( 64 + kk) * 64 + c];
            else if (s == 2) v = p.Wgf[(128 + kk) * 64 + c];
            else if (s == 3) v = p.Wgr[( 64 + kk) * 64 + c];
            else             v = p.Wgr[(128 + kk) * 64 + c];
        } else {
            if (k < 64) v = p.Ws[k * 64 + (c - 64)];
        }
        g_WfinTh[i3] = __float2half_rn(v);
        return;
    }
    int i4 = idx - 98432;
    if (i4 >= 0 && i4 < 128)
        g_bfin[i4] = (i4 < 64) ? (p.bgf[i4] + p.bgr[i4]) : p.bs[i4 - 64];
}

// ---------------- prep: x -> fp16 ----------------------------------------------
__global__ void prep_xh(const float* __restrict__ x) {
    size_t i = (size_t)(blockIdx.x * blockDim.x + threadIdx.x) * 8;
    float4 v0 = *reinterpret_cast<const float4*>(x + i);
    float4 v1 = *reinterpret_cast<const float4*>(x + i + 4);
    uint4 o;
    o.x = packh2(v0.x, v0.y); o.y = packh2(v0.z, v0.w);
    o.z = packh2(v1.x, v1.y); o.w = packh2(v1.z, v1.w);
    *reinterpret_cast<uint4*>(g_xh + i) = o;
}

// =============================================================================
// conv: CTA 128 n x 128 cout, K = 2*min(t+1,7) chunks of 32 — 3-stage pipeline
// =============================================================================
__global__ __launch_bounds__(256, 2) void conv_fp16() {
    extern __shared__ __align__(16) __half smemh[];
    __half* As = smemh;                  // 3 x [128][40]
    __half* Bs = smemh + 3 * 5120;       // 3 x [128][40]
    const uint32_t sA = s2u(As), sB = s2u(Bs);
    const int bt = blockIdx.y, t = bt & 255, n0 = blockIdx.x * 128;
    const int tid = threadIdx.x, w = tid >> 5, lane = tid & 31;
    const int grp = lane >> 2, q = lane & 3;
    const int wM = w & 1, wN = w >> 1;
    const int NC = 2 * ((t + 1 < 7) ? (t + 1) : 7);

    float acc[4][4][4];
#pragma unroll
    for (int a = 0; a < 4; ++a)
#pragma unroll
        for (int b = 0; b < 4; ++b)
#pragma unroll
            for (int c = 0; c < 4; ++c) acc[a][b][c] = 0.f;

#define CONV_ISSUE(kc, buf) {                                                   \
        int d_ = (kc) >> 1, c0_ = ((kc) & 1) * 32;                              \
        const __half* xb = g_xh + ((size_t)(bt - d_) * NNODE + n0) * CC + c0_;  \
        const __half* wb = g_WpadTh + d_ * 8192 + c0_;                          \
        _Pragma("unroll")                                                       \
        for (int i = 0; i < 2; ++i) {                                           \
            int li = tid + i * 256, row = li >> 2, seg = li & 3;                \
            cpa16(sA + ((buf) * 5120 + row * 40 + seg * 8) * 2,                 \
                  xb + (size_t)row * CC + seg * 8);                             \
            cpa16(sB + ((buf) * 5120 + row * 40 + seg * 8) * 2,                 \
                  wb + row * 64 + seg * 8);                                     \
        }                                                                       \
        cp_commit();                                                            \
    }

    CONV_ISSUE(0, 0);
    CONV_ISSUE(1, 1);
    for (int kc = 0; kc < NC; ++kc) {
        if (kc == NC - 1) cp_wait<0>(); else cp_wait<1>();
        __syncthreads();
        if (kc + 2 < NC) {
            int nb = (kc + 2) % 3;
            CONV_ISSUE(kc + 2, nb);
        }
        const __half* Ab = As + (kc % 3) * 5120;
        const __half* Bb = Bs + (kc % 3) * 5120;
#pragma unroll
        for (int ks = 0; ks < 2; ++ks) {
            uint32_t af[4][4], bf[4][2];
#pragma unroll
            for (int mt = 0; mt < 4; ++mt) {
                int row = wM * 64 + mt * 16 + grp;
                af[mt][0] = *(const uint32_t*)&Ab[row * 40 + ks * 16 + 2 * q];
                af[mt][1] = *(const uint32_t*)&Ab[(row + 8) * 40 + ks * 16 + 2 * q];
                af[mt][2] = *(const uint32_t*)&Ab[row * 40 + ks * 16 + 2 * q + 8];
                af[mt][3] = *(const uint32_t*)&Ab[(row + 8) * 40 + ks * 16 + 2 * q + 8];
            }
#pragma unroll
            for (int nt = 0; nt < 4; ++nt) {
                int rb = wN * 32 + nt * 8 + grp;
                bf[nt][0] = *(const uint32_t*)&Bb[rb * 40 + ks * 16 + 2 * q];
                bf[nt][1] = *(const uint32_t*)&Bb[rb * 40 + ks * 16 + 2 * q + 8];
            }
#pragma unroll
            for (int mt = 0; mt < 4; ++mt)
#pragma unroll
                for (int nt = 0; nt < 4; ++nt)
                    mma16(acc[mt][nt], af[mt], bf[nt]);
        }
    }
    __syncthreads();

    // epilogue: gated activation -> stage S[n 128][72], then dual coalesced writes
    __half* S = As;                      // 128*72 = 9216 halves <= 15360
#pragma unroll
    for (int mt = 0; mt < 4; ++mt)
#pragma unroll
        for (int hf = 0; hf < 2; ++hf) {
            int rl = wM * 64 + mt * 16 + grp + hf * 8;
#pragma unroll
            for (int nt = 0; nt < 4; ++nt) {
                int j = wN * 16 + nt * 4 + q;
                float f = acc[mt][nt][hf * 2 + 0] + g_bconv[2 * j];
                float g = acc[mt][nt][hf * 2 + 1] + g_bconv[2 * j + 1];
                float th = 1.f - 2.f / (__expf(2.f * f) + 1.f);
                float sg = 1.f / (1.f + __expf(-g));
                S[rl * 72 + j] = __float2half_rn(th * sg);
            }
        }
    __syncthreads();
#pragma unroll
    for (int i = 0; i < 4; ++i) {        // g_hh [n][f]
        int li = tid + i * 256, row = li >> 3, seg = li & 7;
        *reinterpret_cast<uint4*>(g_hh + ((size_t)bt * NNODE + n0 + row) * CC + seg * 8) =
            *reinterpret_cast<uint4*>(&S[row * 72 + seg * 8]);
    }
#pragma unroll
    for (int i = 0; i < 16; ++i) {       // g_hTh [f][n]
        int li = tid + i * 256, f = li >> 6, np = li & 63;
        uint32_t u = ((uint32_t)__half_as_ushort(S[(2 * np) * 72 + f])) |
                     ((uint32_t)__half_as_ushort(S[(2 * np + 1) * 72 + f]) << 16);
        *reinterpret_cast<uint32_t*>(g_hTh + ((size_t)bt * CC + f) * NNODE + n0 + 2 * np) = u;
    }
}

// =============================================================================
// hop: CTA 256 n x 64 f, K=512, 16 chunks of 32 — 3-stage pipeline
// =============================================================================
__global__ __launch_bounds__(256, 2) void hop_fp16(int dir, int hop) {
    extern __shared__ __align__(16) __half smemh[];
    __half* As = smemh;                  // 3 x [256][40]
    __half* Bs = smemh + 3 * 10240;      // 3 x [64][40]
    const uint32_t sA = s2u(As), sB = s2u(Bs);
    const __half* Aadj = dir ? g_Arh : g_Afh;
    const __half* inT  = hop ? (dir ? g_h1rT : g_h1fT) : g_hTh;
    __half* outR = hop ? (dir ? g_h2r : g_h2f) : (dir ? g_h1rR : g_h1fR);
    __half* outT = dir ? g_h1rT : g_h1fT;

    const int bt = blockIdx.y, n0 = blockIdx.x * 256;
    const int tid = threadIdx.x, w = tid >> 5, lane = tid & 31;
    const int grp = lane >> 2, q = lane & 3;
    const int wM = w & 3, wN = w >> 2;

    float acc[4][4][4];
#pragma unroll
    for (int a = 0; a < 4; ++a)
#pragma unroll
        for (int b = 0; b < 4; ++b)
#pragma unroll
            for (int c = 0; c < 4; ++c) acc[a][b][c] = 0.f;

#define HOP_ISSUE(kc, buf) {                                                    \
        _Pragma("unroll")                                                       \
        for (int i = 0; i < 4; ++i) {                                           \
            int li = tid + i * 256, row = li >> 2, seg = li & 3;                \
            cpa16(sA + ((buf) * 10240 + row * 40 + seg * 8) * 2,                \
                  Aadj + (size_t)(n0 + row) * NNODE + (kc) * 32 + seg * 8);     \
        }                                                                       \
        {                                                                       \
            int row = tid >> 2, seg = tid & 3;                                  \
            cpa16(sB + ((buf) * 2560 + row * 40 + seg * 8) * 2,                 \
                  inT + ((size_t)bt * CC + row) * NNODE + (kc) * 32 + seg * 8); \
        }                                                                       \
        cp_commit();                                                            \
    }

    HOP_ISSUE(0, 0);
    HOP_ISSUE(1, 1);
    for (int kc = 0; kc < 16; ++kc) {
        if (kc == 15) cp_wait<0>(); else cp_wait<1>();
        __syncthreads();
        if (kc + 2 < 16) {
            int nb = (kc + 2) % 3;
            HOP_ISSUE(kc + 2, nb);
        }
        const __half* Ab = As + (kc % 3) * 10240;
        const __half* Bb = Bs + (kc % 3) * 2560;
#pragma unroll
        for (int ks = 0; ks < 2; ++ks) {
            uint32_t af[4][4], bf[4][2];
#pragma unroll
            for (int mt = 0; mt < 4; ++mt) {
                int row = wM * 64 + mt * 16 + grp;
                af[mt][0] = *(const uint32_t*)&Ab[row * 40 + ks * 16 + 2 * q];
                af[mt][1] = *(const uint32_t*)&Ab[(row + 8) * 40 + ks * 16 + 2 * q];
                af[mt][2] = *(const uint32_t*)&Ab[row * 40 + ks * 16 + 2 * q + 8];
                af[mt][3] = *(const uint32_t*)&Ab[(row + 8) * 40 + ks * 16 + 2 * q + 8];
            }
#pragma unroll
            for (int nt = 0; nt < 4; ++nt) {
                int rb = wN * 32 + nt * 8 + grp;
                bf[nt][0] = *(const uint32_t*)&Bb[rb * 40 + ks * 16 + 2 * q];
                bf[nt][1] = *(const uint32_t*)&Bb[rb * 40 + ks * 16 + 2 * q + 8];
            }
#pragma unroll
            for (int mt = 0; mt < 4; ++mt)
#pragma unroll
                for (int nt = 0; nt < 4; ++nt)
                    mma16(acc[mt][nt], af[mt], bf[nt]);
        }
    }
    __syncthreads();

    // stage raw acc (rounded) into S[n 256][72]
    __half* S = As;                      // 256*72 = 18432 halves <= 30720
#pragma unroll
    for (int mt = 0; mt < 4; ++mt)
#pragma unroll
        for (int hf = 0; hf < 2; ++hf) {
            int rl = wM * 64 + mt * 16 + grp + hf * 8;
#pragma unroll
            for (int nt = 0; nt < 4; ++nt) {
                int col = wN * 32 + nt * 8 + 2 * q;
                *reinterpret_cast<uint32_t*>(&S[rl * 72 + col]) =
                    packh2(acc[mt][nt][hf * 2 + 0], acc[mt][nt][hf * 2 + 1]);
            }
        }
    __syncthreads();

    const float om = 1.f - ALPHA;
    // pass 1: outR [n][f], blended with g_hh (all coalesced 16B)
#pragma unroll
    for (int i = 0; i < 8; ++i) {
        int li = tid + i * 256, row = li >> 3, seg = li & 7;
        size_t ga = ((size_t)bt * NNODE + n0 + row) * CC + seg * 8;
        uint4 sa = *reinterpret_cast<uint4*>(&S[row * 72 + seg * 8]);
        uint4 ha = *reinterpret_cast<const uint4*>(g_hh + ga);
        uint4 o;
        uint32_t* sp = &sa.x; uint32_t* hp = &ha.x; uint32_t* op = &o.x;
#pragma unroll
        for (int k = 0; k < 4; ++k) {
            float2 av = unph2(sp[k]), hv = unph2(hp[k]);
            op[k] = packh2(ALPHA * hv.x + om * av.x, ALPHA * hv.y + om * av.y);
        }
        *reinterpret_cast<uint4*>(outR + ga) = o;
    }
    // pass 2 (hop0 only): outT [f][n], blended with g_hTh
    if (hop == 0) {
#pragma unroll
        for (int i = 0; i < 32; ++i) {
            int li = tid + i * 256, f = li >> 7, np = li & 127;
            size_t ga = ((size_t)bt * CC + f) * NNODE + n0 + 2 * np;
            float a0 = __half2float(S[(2 * np) * 72 + f]);
            float a1 = __half2float(S[(2 * np + 1) * 72 + f]);
            float2 hv = unph2(*reinterpret_cast<const uint32_t*>(g_hTh + ga));
            *reinterpret_cast<uint32_t*>(outT + ga) =
                packh2(ALPHA * hv.x + om * a0, ALPHA * hv.y + om * a1);
        }
    }
}

// =============================================================================
// final: CTA 128 rows x 128 cols (64 out + 64 skip), K=320 — 3-stage pipeline
// =============================================================================
__global__ __launch_bounds__(256, 2) void final_fp16(const float* __restrict__ x,
                                                     float* __restrict__ out) {
    extern __shared__ __align__(16) __half smemh[];
    __half* As = smemh;                  // 3 x [128][40]
    __half* Bs = smemh + 3 * 5120;
    const uint32_t sA = s2u(As), sB = s2u(Bs);
    const int r0 = blockIdx.x * 128;
    const int tid = threadIdx.x, w = tid >> 5, lane = tid & 31;
    const int grp = lane >> 2, q = lane & 3;
    const int wM = w & 1, wN = w >> 1;

    float acc[4][4][4];
#pragma unroll
    for (int a = 0; a < 4; ++a)
#pragma unroll
        for (int b = 0; b < 4; ++b)
#pragma unroll
            for (int c = 0; c < 4; ++c) acc[a][b][c] = 0.f;

    const __half* const srcs[5] = {g_hh, g_h1fR, g_h2f, g_h1rR, g_h2r};

#define FIN_ISSUE(kc, buf) {                                                    \
        const __half* sp = srcs[(kc) >> 1] + ((kc) & 1) * 32;                   \
        _Pragma("unroll")                                                       \
        for (int i = 0; i < 2; ++i) {                                           \
            int li = tid + i * 256, row = li >> 2, seg = li & 3;                \
            cpa16(sA + ((buf) * 5120 + row * 40 + seg * 8) * 2,                 \
                  sp + (size_t)(r0 + row) * CC + seg * 8);                      \
            cpa16(sB + ((buf) * 5120 + row * 40 + seg * 8) * 2,                 \
                  g_WfinTh + row * 320 + (kc) * 32 + seg * 8);                  \
        }                                                                       \
        cp_commit();                                                            \
    }

    FIN_ISSUE(0, 0);
    FIN_ISSUE(1, 1);
    for (int kc = 0; kc < 10; ++kc) {
        if (kc == 9) cp_wait<0>(); else cp_wait<1>();
        __syncthreads();
        if (kc + 2 < 10) {
            int nb = (kc + 2) % 3;
            FIN_ISSUE(kc + 2, nb);
        }
        const __half* Ab = As + (kc % 3) * 5120;
        const __half* Bb = Bs + (kc % 3) * 5120;
#pragma unroll
        for (int ks = 0; ks < 2; ++ks) {
            uint32_t af[4][4], bf[4][2];
#pragma unroll
            for (int mt = 0; mt < 4; ++mt) {
                int row = wM * 64 + mt * 16 + grp;
                af[mt][0] = *(const uint32_t*)&Ab[row * 40 + ks * 16 + 2 * q];
                af[mt][1] = *(const uint32_t*)&Ab[(row + 8) * 40 + ks * 16 + 2 * q];
                af[mt][2] = *(const uint32_t*)&Ab[row * 40 + ks * 16 + 2 * q + 8];
                af[mt][3] = *(const uint32_t*)&Ab[(row + 8) * 40 + ks * 16 + 2 * q + 8];
            }
#pragma unroll
            for (int nt = 0; nt < 4; ++nt) {
                int rb = wN * 32 + nt * 8 + grp;
                bf[nt][0] = *(const uint32_t*)&Bb[rb * 40 + ks * 16 + 2 * q];
                bf[nt][1] = *(const uint32_t*)&Bb[rb * 40 + ks * 16 + 2 * q + 8];
            }
#pragma unroll
            for (int mt = 0; mt < 4; ++mt)
#pragma unroll
                for (int nt = 0; nt < 4; ++nt)
                    mma16(acc[mt][nt], af[mt], bf[nt]);
        }
    }

#pragma unroll
    for (int mt = 0; mt < 4; ++mt)
#pragma unroll
        for (int hf = 0; hf < 2; ++hf) {
            int row = r0 + wM * 64 + mt * 16 + grp + hf * 8;
#pragma unroll
            for (int nt = 0; nt < 4; ++nt) {
                int col = wN * 32 + nt * 8 + 2 * q;
                float d0 = acc[mt][nt][hf * 2 + 0] + g_bfin[col];
                float d1 = acc[mt][nt][hf * 2 + 1] + g_bfin[col + 1];
                if (wN < 2) {   // out half: + residual x
                    size_t a = (size_t)row * CC + col;
                    float2 xr = *reinterpret_cast<const float2*>(&x[a]);
                    *reinterpret_cast<float2*>(&out[a]) = make_float2(d0 + xr.x, d1 + xr.y);
                } else {        // skip half
                    size_t a = HN + (size_t)row * CC + (col - 64);
                    *reinterpret_cast<float2*>(&out[a]) = make_float2(d0, d1);
                }
            }
        }
}

// ---------------- launch ------------------------------------------------------
extern "C" void kernel_launch(void* const* d_in, const int* in_sizes, int n_in,
                              void* d_out, int out_size) {
    P p;
    p.x   = (const float*)d_in[0];
    p.adj = (const float*)d_in[1];
    for (int b = 0; b < 4; ++b) {
        p.wf[b] = (const float*)d_in[2 + b * 4 + 0];
        p.bf[b] = (const float*)d_in[2 + b * 4 + 1];
        p.wg[b] = (const float*)d_in[2 + b * 4 + 2];
        p.bg[b] = (const float*)d_in[2 + b * 4 + 3];
    }
    p.Wgf = (const float*)d_in[18];
    p.bgf = (const float*)d_in[19];
    p.Wgr = (const float*)d_in[20];
    p.bgr = (const float*)d_in[21];
    p.Ws  = (const float*)d_in[22];
    p.bs  = (const float*)d_in[23];
    float* out = (float*)d_out;

    const int smemCF = 6 * 5120 * 2;                 // 61440 B (conv/final, 3 bufs)
    const int smemH  = (3 * 10240 + 3 * 2560) * 2;   // 76800 B (hop, 3 bufs)
    cudaFuncSetAttribute(conv_fp16,  cudaFuncAttributeMaxDynamicSharedMemorySize, smemCF);
    cudaFuncSetAttribute(final_fp16, cudaFuncAttributeMaxDynamicSharedMemorySize, smemCF);
    cudaFuncSetAttribute(hop_fp16,   cudaFuncAttributeMaxDynamicSharedMemorySize, smemH);

    prep_adj<<<NNODE, 256>>>(p.adj);
    prep_w<<<385, 256>>>(p);
    prep_xh<<<HN / 8 / 256, 256>>>(p.x);

    dim3 gc(4, BT);
    conv_fp16<<<gc, 256, smemCF>>>();

    dim3 gh(2, BT);
    hop_fp16<<<gh, 256, smemH>>>(0, 0);
    hop_fp16<<<gh, 256, smemH>>>(1, 0);
    hop_fp16<<<gh, 256, smemH>>>(0, 1);
    hop_fp16<<<gh, 256, smemH>>>(1, 1);

    final_fp16<<<BTN / 128, 256, smemCF>>>(p.x, out);
}

// round 9
// speedup vs baseline: 1.0801x; 1.0801x over previous
#include <cuda_runtime.h>
#include <cuda_fp16.h>
#include <cstdint>
#include <math.h>

#define NNODE 512
#define CC 64
#define BT 2048
#define BTN 1048576
#define HN 67108864ULL
#define ALPHA 0.05f

// ---------------- device scratch (half operands, allocation-free) -------------
__device__ __half g_xh  [HN];          // x fp16 [bt][n][c]
__device__ __half g_hh  [HN];          // h [bt][n][f]
__device__ __half g_hTh [HN];          // h [bt][f][n]
__device__ __half g_h1fR[HN];          // hop1 fwd [n][f]
__device__ __half g_h1fT[HN];          // hop1 fwd [f][n]
__device__ __half g_h1rR[HN];
__device__ __half g_h1rT[HN];
__device__ __half g_h2f [HN];          // hop2 [n][f]
__device__ __half g_h2r [HN];
__device__ __half g_Afh [NNODE*NNODE]; // row-norm adj fp16
__device__ __half g_Arh [NNODE*NNODE];
__device__ __half g_WpadTh[7*128*64];  // [d][cout(interleaved 2j=f,2j+1=g)][cin]
__device__ float  g_bconv[128];
__device__ __half g_WfinTh[128*320];   // [cout][k]  cout<64 out, >=64 skip
__device__ float  g_bfin[128];

struct P {
    const float* x; const float* adj;
    const float* wf[4]; const float* bf[4];
    const float* wg[4]; const float* bg[4];
    const float* Wgf; const float* bgf;
    const float* Wgr; const float* bgr;
    const float* Ws;  const float* bs;
};

// ---------------- helpers -----------------------------------------------------
__device__ __forceinline__ void mma16(float* d, const uint32_t* a, const uint32_t* b) {
    asm volatile(
        "mma.sync.aligned.m16n8k16.row.col.f32.f16.f16.f32 "
        "{%0,%1,%2,%3}, {%4,%5,%6,%7}, {%8,%9}, {%0,%1,%2,%3};\n"
        : "+f"(d[0]), "+f"(d[1]), "+f"(d[2]), "+f"(d[3])
        : "r"(a[0]), "r"(a[1]), "r"(a[2]), "r"(a[3]), "r"(b[0]), "r"(b[1]));
}
__device__ __forceinline__ void ldsm4(uint32_t* r, uint32_t addr) {
    asm volatile("ldmatrix.sync.aligned.m8n8.x4.shared.b16 {%0,%1,%2,%3}, [%4];"
        : "=r"(r[0]), "=r"(r[1]), "=r"(r[2]), "=r"(r[3]) : "r"(addr));
}
__device__ __forceinline__ void cpa16(uint32_t dst, const void* src) {
    asm volatile("cp.async.cg.shared.global [%0], [%1], 16;" :: "r"(dst), "l"(src));
}
__device__ __forceinline__ void cp_commit() { asm volatile("cp.async.commit_group;"); }
template<int N> __device__ __forceinline__ void cp_wait() {
    asm volatile("cp.async.wait_group %0;" :: "n"(N) : "memory");
}
__device__ __forceinline__ uint32_t s2u(const void* p) {
    return (uint32_t)__cvta_generic_to_shared(p);
}
__device__ __forceinline__ uint32_t packh2(float a, float b) {
    __half2 h = __floats2half2_rn(a, b);
    return *reinterpret_cast<uint32_t*>(&h);
}
__device__ __forceinline__ float2 unph2(uint32_t u) {
    __half2 h = *reinterpret_cast<__half2*>(&u);
    return __half22float2(h);
}

// Per-lane LDSM source offsets (bytes) for [row][40-half] tiles.
// A-frag tile order: {rows+0 k0, rows+8 k0, rows+0 k+8, rows+8 k+8}
__device__ __forceinline__ uint32_t laneA_off(int RA, int lane) {
    int t = lane >> 3;
    return (uint32_t)(((RA + (t & 1) * 8 + (lane & 7)) * 40 + (t >> 1) * 8) * 2);
}
// B-frag tile order: {cols+0 k0, cols+0 k+8, cols+8 k0, cols+8 k+8}
__device__ __forceinline__ uint32_t laneB_off(int CB, int lane) {
    int t = lane >> 3;
    return (uint32_t)(((CB + (t >> 1) * 8 + (lane & 7)) * 40 + (t & 1) * 8) * 2);
}

// ---------------- prep: adjacencies (fp16) ------------------------------------
__global__ void prep_adj(const float* __restrict__ adj) {
    int n = blockIdx.x, tid = threadIdx.x;
    __shared__ float red[256];
    float s1 = 0.f, s2 = 0.f;
    for (int m = tid; m < NNODE; m += 256) {
        s1 += adj[n * NNODE + m];
        s2 += adj[m * NNODE + n];
    }
    red[tid] = s1; __syncthreads();
    for (int k = 128; k; k >>= 1) { if (tid < k) red[tid] += red[tid + k]; __syncthreads(); }
    float inv1 = 1.f / fmaxf(red[0] + 1.f, 1e-9f);
    __syncthreads();
    red[tid] = s2; __syncthreads();
    for (int k = 128; k; k >>= 1) { if (tid < k) red[tid] += red[tid + k]; __syncthreads(); }
    float inv2 = 1.f / fmaxf(red[0] + 1.f, 1e-9f);
    for (int m = tid; m < NNODE; m += 256) {
        g_Afh[n * NNODE + m] = __float2half_rn((adj[n * NNODE + m] + (m == n ? 1.f : 0.f)) * inv1);
        g_Arh[n * NNODE + m] = __float2half_rn((adj[m * NNODE + n] + (m == n ? 1.f : 0.f)) * inv2);
    }
}

// ---------------- prep: weights ------------------------------------------------
__global__ void prep_w(P p) {
    int idx = blockIdx.x * blockDim.x + threadIdx.x;
    const int KR[4] = {2, 3, 6, 7};
    if (idx < 57344) {                   // WpadTh[d][c][cin]
        int d = idx / 8192;
        int c = (idx >> 6) & 127;
        int cin = idx & 63;
        int j = c >> 1, gsel = c & 1;
        int i = j >> 4, r = j & 15;
        int k = KR[i], jj = k - 1 - d;
        float v = 0.f;
        if (jj >= 0) {
            const float* w = gsel ? p.wg[i] : p.wf[i];
            v = w[(jj * 64 + cin) * 16 + r];
        }
        g_WpadTh[idx] = __float2half_rn(v);
        return;
    }
    int i2 = idx - 57344;
    if (i2 < 128) {
        int j = i2 >> 1, gsel = i2 & 1;
        int i = j >> 4, r = j & 15;
        g_bconv[i2] = gsel ? p.bg[i][r] : p.bf[i][r];
        return;
    }
    int i3 = idx - 57472;
    if (i3 < 40960) {                    // WfinTh[c][k]
        int c = i3 / 320, k = i3 % 320;
        float v = 0.f;
        if (c < 64) {
            int s = k >> 6, kk = k & 63;
            if      (s == 0) v = p.Wgf[kk * 64 + c] + p.Wgr[kk * 64 + c];
            else if (s == 1) v = p.Wgf[( 64 + kk) * 64 + c];
            else if (s == 2) v = p.Wgf[(128 + kk) * 64 + c];
            else if (s == 3) v = p.Wgr[( 64 + kk) * 64 + c];
            else             v = p.Wgr[(128 + kk) * 64 + c];
        } else {
            if (k < 64) v = p.Ws[k * 64 + (c - 64)];
        }
        g_WfinTh[i3] = __float2half_rn(v);
        return;
    }
    int i4 = idx - 98432;
    if (i4 >= 0 && i4 < 128)
        g_bfin[i4] = (i4 < 64) ? (p.bgf[i4] + p.bgr[i4]) : p.bs[i4 - 64];
}

// ---------------- prep: x -> fp16 ----------------------------------------------
__global__ void prep_xh(const float* __restrict__ x) {
    size_t i = (size_t)(blockIdx.x * blockDim.x + threadIdx.x) * 8;
    float4 v0 = *reinterpret_cast<const float4*>(x + i);
    float4 v1 = *reinterpret_cast<const float4*>(x + i + 4);
    uint4 o;
    o.x = packh2(v0.x, v0.y); o.y = packh2(v0.z, v0.w);
    o.z = packh2(v1.x, v1.y); o.w = packh2(v1.z, v1.w);
    *reinterpret_cast<uint4*>(g_xh + i) = o;
}

// =============================================================================
// conv: CTA 128 n x 128 cout, K = 2*min(t+1,7) chunks of 32
// =============================================================================
__global__ __launch_bounds__(256, 2) void conv_fp16() {
    extern __shared__ __align__(16) __half smemh[];
    __half* As = smemh;                  // 2 x [128][40]
    __half* Bs = smemh + 2 * 5120;       // 2 x [128][40]
    const uint32_t sA = s2u(As), sB = s2u(Bs);
    const int bt = blockIdx.y, t = bt & 255, n0 = blockIdx.x * 128;
    const int tid = threadIdx.x, w = tid >> 5, lane = tid & 31;
    const int grp = lane >> 2, q = lane & 3;
    const int wM = w & 1, wN = w >> 1;
    const int NC = 2 * ((t + 1 < 7) ? (t + 1) : 7);
    const uint32_t lA = laneA_off(wM * 64, lane);
    const uint32_t lB = laneB_off(wN * 32, lane);

    float acc[4][4][4];
#pragma unroll
    for (int a = 0; a < 4; ++a)
#pragma unroll
        for (int b = 0; b < 4; ++b)
#pragma unroll
            for (int c = 0; c < 4; ++c) acc[a][b][c] = 0.f;

#define CONV_ISSUE(kc, buf) {                                                   \
        int d_ = (kc) >> 1, c0_ = ((kc) & 1) * 32;                              \
        const __half* xb = g_xh + ((size_t)(bt - d_) * NNODE + n0) * CC + c0_;  \
        const __half* wb = g_WpadTh + d_ * 8192 + c0_;                          \
        _Pragma("unroll")                                                       \
        for (int i = 0; i < 2; ++i) {                                           \
            int li = tid + i * 256, row = li >> 2, seg = li & 3;                \
            cpa16(sA + ((buf) * 5120 + row * 40 + seg * 8) * 2,                 \
                  xb + (size_t)row * CC + seg * 8);                             \
            cpa16(sB + ((buf) * 5120 + row * 40 + seg * 8) * 2,                 \
                  wb + row * 64 + seg * 8);                                     \
        }                                                                       \
        cp_commit();                                                            \
    }

    CONV_ISSUE(0, 0);
    for (int kc = 0; kc < NC; ++kc) {
        if (kc + 1 < NC) { CONV_ISSUE(kc + 1, (kc + 1) & 1); cp_wait<1>(); }
        else cp_wait<0>();
        __syncthreads();
        const uint32_t aB = sA + (kc & 1) * 10240 + lA;
        const uint32_t bB = sB + (kc & 1) * 10240 + lB;
#pragma unroll
        for (int ks = 0; ks < 2; ++ks) {
            uint32_t af[4][4], bq[2][4];
#pragma unroll
            for (int mt = 0; mt < 4; ++mt) ldsm4(af[mt], aB + mt * 1280 + ks * 32);
#pragma unroll
            for (int j = 0; j < 2; ++j)    ldsm4(bq[j], bB + j * 1280 + ks * 32);
#pragma unroll
            for (int mt = 0; mt < 4; ++mt)
#pragma unroll
                for (int nt = 0; nt < 4; ++nt)
                    mma16(acc[mt][nt], af[mt], &bq[nt >> 1][(nt & 1) * 2]);
        }
        __syncthreads();
    }

    // epilogue: gated activation -> stage S[n 128][72], then dual coalesced writes
    __half* S = As;
#pragma unroll
    for (int mt = 0; mt < 4; ++mt)
#pragma unroll
        for (int hf = 0; hf < 2; ++hf) {
            int rl = wM * 64 + mt * 16 + grp + hf * 8;
#pragma unroll
            for (int nt = 0; nt < 4; ++nt) {
                int j = wN * 16 + nt * 4 + q;
                float f = acc[mt][nt][hf * 2 + 0] + g_bconv[2 * j];
                float g = acc[mt][nt][hf * 2 + 1] + g_bconv[2 * j + 1];
                float th = 1.f - 2.f / (__expf(2.f * f) + 1.f);
                float sg = 1.f / (1.f + __expf(-g));
                S[rl * 72 + j] = __float2half_rn(th * sg);
            }
        }
    __syncthreads();
#pragma unroll
    for (int i = 0; i < 4; ++i) {        // g_hh [n][f]
        int li = tid + i * 256, row = li >> 3, seg = li & 7;
        *reinterpret_cast<uint4*>(g_hh + ((size_t)bt * NNODE + n0 + row) * CC + seg * 8) =
            *reinterpret_cast<uint4*>(&S[row * 72 + seg * 8]);
    }
#pragma unroll
    for (int i = 0; i < 16; ++i) {       // g_hTh [f][n]
        int li = tid + i * 256, f = li >> 6, np = li & 63;
        uint32_t u = ((uint32_t)__half_as_ushort(S[(2 * np) * 72 + f])) |
                     ((uint32_t)__half_as_ushort(S[(2 * np + 1) * 72 + f]) << 16);
        *reinterpret_cast<uint32_t*>(g_hTh + ((size_t)bt * CC + f) * NNODE + n0 + 2 * np) = u;
    }
}

// =============================================================================
// hop: CTA 256 n x 64 f, K=512, dir = blockIdx.z. out = alpha*h+(1-alpha)*A@hin
// =============================================================================
__global__ __launch_bounds__(256, 2) void hop_fp16(int hop) {
    extern __shared__ __align__(16) __half smemh[];
    __half* As = smemh;                  // 2 x [256][40]
    __half* Bs = smemh + 2 * 10240;      // 2 x [64][40]
    const uint32_t sA = s2u(As), sB = s2u(Bs);
    const int dir = blockIdx.z;
    const __half* Aadj = dir ? g_Arh : g_Afh;
    const __half* inT  = hop ? (dir ? g_h1rT : g_h1fT) : g_hTh;
    __half* outR = hop ? (dir ? g_h2r : g_h2f) : (dir ? g_h1rR : g_h1fR);
    __half* outT = dir ? g_h1rT : g_h1fT;

    const int bt = blockIdx.y, n0 = blockIdx.x * 256;
    const int tid = threadIdx.x, w = tid >> 5, lane = tid & 31;
    const int grp = lane >> 2, q = lane & 3;
    const int wM = w & 3, wN = w >> 2;
    const uint32_t lA = laneA_off(wM * 64, lane);
    const uint32_t lB = laneB_off(wN * 32, lane);

    float acc[4][4][4];
#pragma unroll
    for (int a = 0; a < 4; ++a)
#pragma unroll
        for (int b = 0; b < 4; ++b)
#pragma unroll
            for (int c = 0; c < 4; ++c) acc[a][b][c] = 0.f;

#define HOP_ISSUE(kc, buf) {                                                    \
        _Pragma("unroll")                                                       \
        for (int i = 0; i < 4; ++i) {                                           \
            int li = tid + i * 256, row = li >> 2, seg = li & 3;                \
            cpa16(sA + ((buf) * 10240 + row * 40 + seg * 8) * 2,                \
                  Aadj + (size_t)(n0 + row) * NNODE + (kc) * 32 + seg * 8);     \
        }                                                                       \
        {                                                                       \
            int row = tid >> 2, seg = tid & 3;                                  \
            cpa16(sB + ((buf) * 2560 + row * 40 + seg * 8) * 2,                 \
                  inT + ((size_t)bt * CC + row) * NNODE + (kc) * 32 + seg * 8); \
        }                                                                       \
        cp_commit();                                                            \
    }

    HOP_ISSUE(0, 0);
    for (int kc = 0; kc < 16; ++kc) {
        if (kc + 1 < 16) { HOP_ISSUE(kc + 1, (kc + 1) & 1); cp_wait<1>(); }
        else cp_wait<0>();
        __syncthreads();
        const uint32_t aB = sA + (kc & 1) * 20480 + lA;
        const uint32_t bB = sB + (kc & 1) * 5120 + lB;
#pragma unroll
        for (int ks = 0; ks < 2; ++ks) {
            uint32_t af[4][4], bq[2][4];
#pragma unroll
            for (int mt = 0; mt < 4; ++mt) ldsm4(af[mt], aB + mt * 1280 + ks * 32);
#pragma unroll
            for (int j = 0; j < 2; ++j)    ldsm4(bq[j], bB + j * 1280 + ks * 32);
#pragma unroll
            for (int mt = 0; mt < 4; ++mt)
#pragma unroll
                for (int nt = 0; nt < 4; ++nt)
                    mma16(acc[mt][nt], af[mt], &bq[nt >> 1][(nt & 1) * 2]);
        }
        __syncthreads();
    }

    // stage raw acc (rounded) into S[n 256][72]
    __half* S = As;
#pragma unroll
    for (int mt = 0; mt < 4; ++mt)
#pragma unroll
        for (int hf = 0; hf < 2; ++hf) {
            int rl = wM * 64 + mt * 16 + grp + hf * 8;
#pragma unroll
            for (int nt = 0; nt < 4; ++nt) {
                int col = wN * 32 + nt * 8 + 2 * q;
                *reinterpret_cast<uint32_t*>(&S[rl * 72 + col]) =
                    packh2(acc[mt][nt][hf * 2 + 0], acc[mt][nt][hf * 2 + 1]);
            }
        }
    __syncthreads();

    const float om = 1.f - ALPHA;
    // pass 1: outR [n][f], blended with g_hh (all coalesced 16B)
#pragma unroll
    for (int i = 0; i < 8; ++i) {
        int li = tid + i * 256, row = li >> 3, seg = li & 7;
        size_t ga = ((size_t)bt * NNODE + n0 + row) * CC + seg * 8;
        uint4 sa = *reinterpret_cast<uint4*>(&S[row * 72 + seg * 8]);
        uint4 ha = *reinterpret_cast<const uint4*>(g_hh + ga);
        uint4 o;
        uint32_t* sp = &sa.x; uint32_t* hp = &ha.x; uint32_t* op = &o.x;
#pragma unroll
        for (int k = 0; k < 4; ++k) {
            float2 av = unph2(sp[k]), hv = unph2(hp[k]);
            op[k] = packh2(ALPHA * hv.x + om * av.x, ALPHA * hv.y + om * av.y);
        }
        *reinterpret_cast<uint4*>(outR + ga) = o;
    }
    // pass 2 (hop0 only): outT [f][n], blended with g_hTh
    if (hop == 0) {
#pragma unroll
        for (int i = 0; i < 32; ++i) {
            int li = tid + i * 256, f = li >> 7, np = li & 127;
            size_t ga = ((size_t)bt * CC + f) * NNODE + n0 + 2 * np;
            float a0 = __half2float(S[(2 * np) * 72 + f]);
            float a1 = __half2float(S[(2 * np + 1) * 72 + f]);
            float2 hv = unph2(*reinterpret_cast<const uint32_t*>(g_hTh + ga));
            *reinterpret_cast<uint32_t*>(outT + ga) =
                packh2(ALPHA * hv.x + om * a0, ALPHA * hv.y + om * a1);
        }
    }
}

// =============================================================================
// final: CTA 128 rows x 128 cols (64 out + 64 skip), K=320
// =============================================================================
__global__ __launch_bounds__(256, 2) void final_fp16(const float* __restrict__ x,
                                                     float* __restrict__ out) {
    extern __shared__ __align__(16) __half smemh[];
    __half* As = smemh;                  // 2 x [128][40]
    __half* Bs = smemh + 2 * 5120;
    const uint32_t sA = s2u(As), sB = s2u(Bs);
    const int r0 = blockIdx.x * 128;
    const int tid = threadIdx.x, w = tid >> 5, lane = tid & 31;
    const int grp = lane >> 2, q = lane & 3;
    const int wM = w & 1, wN = w >> 1;
    const uint32_t lA = laneA_off(wM * 64, lane);
    const uint32_t lB = laneB_off(wN * 32, lane);

    float acc[4][4][4];
#pragma unroll
    for (int a = 0; a < 4; ++a)
#pragma unroll
        for (int b = 0; b < 4; ++b)
#pragma unroll
            for (int c = 0; c < 4; ++c) acc[a][b][c] = 0.f;

    const __half* const srcs[5] = {g_hh, g_h1fR, g_h2f, g_h1rR, g_h2r};

#define FIN_ISSUE(kc, buf) {                                                    \
        const __half* sp = srcs[(kc) >> 1] + ((kc) & 1) * 32;                   \
        _Pragma("unroll")                                                       \
        for (int i = 0; i < 2; ++i) {                                           \
            int li = tid + i * 256, row = li >> 2, seg = li & 3;                \
            cpa16(sA + ((buf) * 5120 + row * 40 + seg * 8) * 2,                 \
                  sp + (size_t)(r0 + row) * CC + seg * 8);                      \
            cpa16(sB + ((buf) * 5120 + row * 40 + seg * 8) * 2,                 \
                  g_WfinTh + row * 320 + (kc) * 32 + seg * 8);                  \
        }                                                                       \
        cp_commit();                                                            \
    }

    FIN_ISSUE(0, 0);
    for (int kc = 0; kc < 10; ++kc) {
        if (kc + 1 < 10) { FIN_ISSUE(kc + 1, (kc + 1) & 1); cp_wait<1>(); }
        else cp_wait<0>();
        __syncthreads();
        const uint32_t aB = sA + (kc & 1) * 10240 + lA;
        const uint32_t bB = sB + (kc & 1) * 10240 + lB;
#pragma unroll
        for (int ks = 0; ks < 2; ++ks) {
            uint32_t af[4][4], bq[2][4];
#pragma unroll
            for (int mt = 0; mt < 4; ++mt) ldsm4(af[mt], aB + mt * 1280 + ks * 32);
#pragma unroll
            for (int j = 0; j < 2; ++j)    ldsm4(bq[j], bB + j * 1280 + ks * 32);
#pragma unroll
            for (int mt = 0; mt < 4; ++mt)
#pragma unroll
                for (int nt = 0; nt < 4; ++nt)
                    mma16(acc[mt][nt], af[mt], &bq[nt >> 1][(nt & 1) * 2]);
        }
        __syncthreads();
    }

#pragma unroll
    for (int mt = 0; mt < 4; ++mt)
#pragma unroll
        for (int hf = 0; hf < 2; ++hf) {
            int row = r0 + wM * 64 + mt * 16 + grp + hf * 8;
#pragma unroll
            for (int nt = 0; nt < 4; ++nt) {
                int col = wN * 32 + nt * 8 + 2 * q;
                float d0 = acc[mt][nt][hf * 2 + 0] + g_bfin[col];
                float d1 = acc[mt][nt][hf * 2 + 1] + g_bfin[col + 1];
                if (wN < 2) {   // out half: + residual x
                    size_t a = (size_t)row * CC + col;
                    float2 xr = *reinterpret_cast<const float2*>(&x[a]);
                    *reinterpret_cast<float2*>(&out[a]) = make_float2(d0 + xr.x, d1 + xr.y);
                } else {        // skip half
                    size_t a = HN + (size_t)row * CC + (col - 64);
                    *reinterpret_cast<float2*>(&out[a]) = make_float2(d0, d1);
                }
            }
        }
}

// ---------------- launch ------------------------------------------------------
extern "C" void kernel_launch(void* const* d_in, const int* in_sizes, int n_in,
                              void* d_out, int out_size) {
    P p;
    p.x   = (const float*)d_in[0];
    p.adj = (const float*)d_in[1];
    for (int b = 0; b < 4; ++b) {
        p.wf[b] = (const float*)d_in[2 + b * 4 + 0];
        p.bf[b] = (const float*)d_in[2 + b * 4 + 1];
        p.wg[b] = (const float*)d_in[2 + b * 4 + 2];
        p.bg[b] = (const float*)d_in[2 + b * 4 + 3];
    }
    p.Wgf = (const float*)d_in[18];
    p.bgf = (const float*)d_in[19];
    p.Wgr = (const float*)d_in[20];
    p.bgr = (const float*)d_in[21];
    p.Ws  = (const float*)d_in[22];
    p.bs  = (const float*)d_in[23];
    float* out = (float*)d_out;

    const int smemCF = 4 * 5120 * 2;                 // 40960 B
    const int smemH  = (2 * 10240 + 2 * 2560) * 2;   // 51200 B
    cudaFuncSetAttribute(hop_fp16, cudaFuncAttributeMaxDynamicSharedMemorySize, smemH);

    prep_adj<<<NNODE, 256>>>(p.adj);
    prep_w<<<385, 256>>>(p);
    prep_xh<<<HN / 8 / 256, 256>>>(p.x);

    dim3 gc(4, BT);
    conv_fp16<<<gc, 256, smemCF>>>();

    dim3 gh(2, BT, 2);
    hop_fp16<<<gh, 256, smemH>>>(0);
    hop_fp16<<<gh, 256, smemH>>>(1);

    final_fp16<<<BTN / 128, 256, smemCF>>>(p.x, out);
}

// round 10
// speedup vs baseline: 1.1911x; 1.1028x over previous
#include <cuda_runtime.h>
#include <cuda_fp16.h>
#include <cstdint>
#include <math.h>

#define NNODE 512
#define CC 64
#define BT 2048
#define BTN 1048576
#define HN 67108864ULL
#define ALPHA 0.05f

// tile row stride in halves (64 data + 8 pad)
#define RS 72

// ---------------- device scratch (half operands, allocation-free) -------------
__device__ __half g_xh  [HN];          // x fp16 [bt][n][c]
__device__ __half g_hh  [HN];          // h [bt][n][f]
__device__ __half g_hTh [HN];          // h [bt][f][n]
__device__ __half g_h1fR[HN];          // hop1 fwd [n][f]
__device__ __half g_h1fT[HN];          // hop1 fwd [f][n]
__device__ __half g_h1rR[HN];
__device__ __half g_h1rT[HN];
__device__ __half g_h2f [HN];          // hop2 [n][f]
__device__ __half g_h2r [HN];
__device__ __half g_Afh [NNODE*NNODE]; // row-norm adj fp16
__device__ __half g_Arh [NNODE*NNODE];
__device__ __half g_WpadTh[7*128*64];  // [d][cout(interleaved 2j=f,2j+1=g)][cin]
__device__ float  g_bconv[128];
__device__ __half g_WfinTh[128*320];   // [cout][k]  cout<64 out, >=64 skip
__device__ float  g_bfin[128];

struct P {
    const float* x; const float* adj;
    const float* wf[4]; const float* bf[4];
    const float* wg[4]; const float* bg[4];
    const float* Wgf; const float* bgf;
    const float* Wgr; const float* bgr;
    const float* Ws;  const float* bs;
};

// ---------------- helpers -----------------------------------------------------
__device__ __forceinline__ void mma16(float* d, const uint32_t* a, const uint32_t* b) {
    asm volatile(
        "mma.sync.aligned.m16n8k16.row.col.f32.f16.f16.f32 "
        "{%0,%1,%2,%3}, {%4,%5,%6,%7}, {%8,%9}, {%0,%1,%2,%3};\n"
        : "+f"(d[0]), "+f"(d[1]), "+f"(d[2]), "+f"(d[3])
        : "r"(a[0]), "r"(a[1]), "r"(a[2]), "r"(a[3]), "r"(b[0]), "r"(b[1]));
}
__device__ __forceinline__ void ldsm4(uint32_t* r, uint32_t addr) {
    asm volatile("ldmatrix.sync.aligned.m8n8.x4.shared.b16 {%0,%1,%2,%3}, [%4];"
        : "=r"(r[0]), "=r"(r[1]), "=r"(r[2]), "=r"(r[3]) : "r"(addr));
}
__device__ __forceinline__ void cpa16(uint32_t dst, const void* src) {
    asm volatile("cp.async.cg.shared.global [%0], [%1], 16;" :: "r"(dst), "l"(src));
}
__device__ __forceinline__ void cp_commit() { asm volatile("cp.async.commit_group;"); }
template<int N> __device__ __forceinline__ void cp_wait() {
    asm volatile("cp.async.wait_group %0;" :: "n"(N) : "memory");
}
__device__ __forceinline__ uint32_t s2u(const void* p) {
    return (uint32_t)__cvta_generic_to_shared(p);
}
__device__ __forceinline__ uint32_t packh2(float a, float b) {
    __half2 h = __floats2half2_rn(a, b);
    return *reinterpret_cast<uint32_t*>(&h);
}
__device__ __forceinline__ float2 unph2(uint32_t u) {
    __half2 h = *reinterpret_cast<__half2*>(&u);
    return __half22float2(h);
}

// Per-lane LDSM source offsets (bytes) for [row][RS-half] tiles.
// A-frag tile order: {rows+0 k0, rows+8 k0, rows+0 k+8, rows+8 k+8}
__device__ __forceinline__ uint32_t laneA_off(int RA, int lane) {
    int t = lane >> 3;
    return (uint32_t)(((RA + (t & 1) * 8 + (lane & 7)) * RS + (t >> 1) * 8) * 2);
}
// B-frag tile order: {cols+0 k0, cols+0 k+8, cols+8 k0, cols+8 k+8}
__device__ __forceinline__ uint32_t laneB_off(int CB, int lane) {
    int t = lane >> 3;
    return (uint32_t)(((CB + (t >> 1) * 8 + (lane & 7)) * RS + (t & 1) * 8) * 2);
}

// ---------------- prep: adjacencies (fp16) ------------------------------------
__global__ void prep_adj(const float* __restrict__ adj) {
    int n = blockIdx.x, tid = threadIdx.x;
    __shared__ float red[256];
    float s1 = 0.f, s2 = 0.f;
    for (int m = tid; m < NNODE; m += 256) {
        s1 += adj[n * NNODE + m];
        s2 += adj[m * NNODE + n];
    }
    red[tid] = s1; __syncthreads();
    for (int k = 128; k; k >>= 1) { if (tid < k) red[tid] += red[tid + k]; __syncthreads(); }
    float inv1 = 1.f / fmaxf(red[0] + 1.f, 1e-9f);
    __syncthreads();
    red[tid] = s2; __syncthreads();
    for (int k = 128; k; k >>= 1) { if (tid < k) red[tid] += red[tid + k]; __syncthreads(); }
    float inv2 = 1.f / fmaxf(red[0] + 1.f, 1e-9f);
    for (int m = tid; m < NNODE; m += 256) {
        g_Afh[n * NNODE + m] = __float2half_rn((adj[n * NNODE + m] + (m == n ? 1.f : 0.f)) * inv1);
        g_Arh[n * NNODE + m] = __float2half_rn((adj[m * NNODE + n] + (m == n ? 1.f : 0.f)) * inv2);
    }
}

// ---------------- prep: weights ------------------------------------------------
__global__ void prep_w(P p) {
    int idx = blockIdx.x * blockDim.x + threadIdx.x;
    const int KR[4] = {2, 3, 6, 7};
    if (idx < 57344) {                   // WpadTh[d][c][cin]
        int d = idx / 8192;
        int c = (idx >> 6) & 127;
        int cin = idx & 63;
        int j = c >> 1, gsel = c & 1;
        int i = j >> 4, r = j & 15;
        int k = KR[i], jj = k - 1 - d;
        float v = 0.f;
        if (jj >= 0) {
            const float* w = gsel ? p.wg[i] : p.wf[i];
            v = w[(jj * 64 + cin) * 16 + r];
        }
        g_WpadTh[idx] = __float2half_rn(v);
        return;
    }
    int i2 = idx - 57344;
    if (i2 < 128) {
        int j = i2 >> 1, gsel = i2 & 1;
        int i = j >> 4, r = j & 15;
        g_bconv[i2] = gsel ? p.bg[i][r] : p.bf[i][r];
        return;
    }
    int i3 = idx - 57472;
    if (i3 < 40960) {                    // WfinTh[c][k]
        int c = i3 / 320, k = i3 % 320;
        float v = 0.f;
        if (c < 64) {
            int s = k >> 6, kk = k & 63;
            if      (s == 0) v = p.Wgf[kk * 64 + c] + p.Wgr[kk * 64 + c];
            else if (s == 1) v = p.Wgf[( 64 + kk) * 64 + c];
            else if (s == 2) v = p.Wgf[(128 + kk) * 64 + c];
            else if (s == 3) v = p.Wgr[( 64 + kk) * 64 + c];
            else             v = p.Wgr[(128 + kk) * 64 + c];
        } else {
            if (k < 64) v = p.Ws[k * 64 + (c - 64)];
        }
        g_WfinTh[i3] = __float2half_rn(v);
        return;
    }
    int i4 = idx - 98432;
    if (i4 >= 0 && i4 < 128)
        g_bfin[i4] = (i4 < 64) ? (p.bgf[i4] + p.bgr[i4]) : p.bs[i4 - 64];
}

// ---------------- prep: x -> fp16 ----------------------------------------------
__global__ void prep_xh(const float* __restrict__ x) {
    size_t i = (size_t)(blockIdx.x * blockDim.x + threadIdx.x) * 8;
    float4 v0 = *reinterpret_cast<const float4*>(x + i);
    float4 v1 = *reinterpret_cast<const float4*>(x + i + 4);
    uint4 o;
    o.x = packh2(v0.x, v0.y); o.y = packh2(v0.z, v0.w);
    o.z = packh2(v1.x, v1.y); o.w = packh2(v1.z, v1.w);
    *reinterpret_cast<uint4*>(g_xh + i) = o;
}

// mainloop body shared by all kernels: 4 ks steps over a K=64 chunk
#define MMA_CHUNK(aB, bB) {                                                     \
        _Pragma("unroll")                                                       \
        for (int ks = 0; ks < 4; ++ks) {                                        \
            uint32_t af[4][4], bq[2][4];                                        \
            _Pragma("unroll")                                                   \
            for (int mt = 0; mt < 4; ++mt) ldsm4(af[mt], (aB) + mt * (16*RS*2) + ks * 32); \
            _Pragma("unroll")                                                   \
            for (int j = 0; j < 2; ++j)    ldsm4(bq[j], (bB) + j * (16*RS*2) + ks * 32);   \
            _Pragma("unroll")                                                   \
            for (int mt = 0; mt < 4; ++mt)                                      \
                _Pragma("unroll")                                               \
                for (int nt = 0; nt < 4; ++nt)                                  \
                    mma16(acc[mt][nt], af[mt], &bq[nt >> 1][(nt & 1) * 2]);     \
        }                                                                       \
    }

// =============================================================================
// conv: CTA 128 n x 128 cout, K = min(t+1,7) chunks of 64 (one per tap d)
// =============================================================================
#define CONV_BUF (128 * RS)            // halves per tile buffer
__global__ __launch_bounds__(256, 2) void conv_fp16() {
    extern __shared__ __align__(16) __half smemh[];
    __half* As = smemh;                  // 2 x [128][RS]
    __half* Bs = smemh + 2 * CONV_BUF;   // 2 x [128][RS]
    const uint32_t sA = s2u(As), sB = s2u(Bs);
    const int bt = blockIdx.y, t = bt & 255, n0 = blockIdx.x * 128;
    const int tid = threadIdx.x, w = tid >> 5, lane = tid & 31;
    const int grp = lane >> 2, q = lane & 3;
    const int wM = w & 1, wN = w >> 1;
    const int NC = (t + 1 < 7) ? (t + 1) : 7;
    const uint32_t lA = laneA_off(wM * 64, lane);
    const uint32_t lB = laneB_off(wN * 32, lane);

    float acc[4][4][4];
#pragma unroll
    for (int a = 0; a < 4; ++a)
#pragma unroll
        for (int b = 0; b < 4; ++b)
#pragma unroll
            for (int c = 0; c < 4; ++c) acc[a][b][c] = 0.f;

#define CONV_ISSUE(kc, buf) {                                                   \
        const __half* xb = g_xh + ((size_t)(bt - (kc)) * NNODE + n0) * CC;      \
        const __half* wb = g_WpadTh + (kc) * 8192;                              \
        _Pragma("unroll")                                                       \
        for (int i = 0; i < 4; ++i) {                                           \
            int li = tid + i * 256, row = li >> 3, seg = li & 7;                \
            cpa16(sA + ((buf) * CONV_BUF + row * RS + seg * 8) * 2,             \
                  xb + (size_t)row * CC + seg * 8);                             \
            cpa16(sB + ((buf) * CONV_BUF + row * RS + seg * 8) * 2,             \
                  wb + row * 64 + seg * 8);                                     \
        }                                                                       \
        cp_commit();                                                            \
    }

    CONV_ISSUE(0, 0);
    for (int kc = 0; kc < NC; ++kc) {
        if (kc + 1 < NC) { CONV_ISSUE(kc + 1, (kc + 1) & 1); cp_wait<1>(); }
        else cp_wait<0>();
        __syncthreads();
        MMA_CHUNK(sA + (kc & 1) * CONV_BUF * 2 + lA,
                  sB + (kc & 1) * CONV_BUF * 2 + lB);
        __syncthreads();
    }

    // epilogue: gated activation -> stage S[n 128][RS], then dual coalesced writes
    __half* S = As;
#pragma unroll
    for (int mt = 0; mt < 4; ++mt)
#pragma unroll
        for (int hf = 0; hf < 2; ++hf) {
            int rl = wM * 64 + mt * 16 + grp + hf * 8;
#pragma unroll
            for (int nt = 0; nt < 4; ++nt) {
                int j = wN * 16 + nt * 4 + q;
                float f = acc[mt][nt][hf * 2 + 0] + g_bconv[2 * j];
                float g = acc[mt][nt][hf * 2 + 1] + g_bconv[2 * j + 1];
                float th = 1.f - 2.f / (__expf(2.f * f) + 1.f);
                float sg = 1.f / (1.f + __expf(-g));
                S[rl * RS + j] = __float2half_rn(th * sg);
            }
        }
    __syncthreads();
#pragma unroll
    for (int i = 0; i < 4; ++i) {        // g_hh [n][f]
        int li = tid + i * 256, row = li >> 3, seg = li & 7;
        *reinterpret_cast<uint4*>(g_hh + ((size_t)bt * NNODE + n0 + row) * CC + seg * 8) =
            *reinterpret_cast<uint4*>(&S[row * RS + seg * 8]);
    }
#pragma unroll
    for (int i = 0; i < 16; ++i) {       // g_hTh [f][n]
        int li = tid + i * 256, f = li >> 6, np = li & 63;
        uint32_t u = ((uint32_t)__half_as_ushort(S[(2 * np) * RS + f])) |
                     ((uint32_t)__half_as_ushort(S[(2 * np + 1) * RS + f]) << 16);
        *reinterpret_cast<uint32_t*>(g_hTh + ((size_t)bt * CC + f) * NNODE + n0 + 2 * np) = u;
    }
}

// =============================================================================
// hop: CTA 256 n x 64 f, K=512 in 8 chunks of 64, dir = blockIdx.z
// =============================================================================
#define HOPA_BUF (256 * RS)
#define HOPB_BUF (64 * RS)
__global__ __launch_bounds__(256, 2) void hop_fp16(int hop) {
    extern __shared__ __align__(16) __half smemh[];
    __half* As = smemh;                  // 2 x [256][RS]
    __half* Bs = smemh + 2 * HOPA_BUF;   // 2 x [64][RS]
    const uint32_t sA = s2u(As), sB = s2u(Bs);
    const int dir = blockIdx.z;
    const __half* Aadj = dir ? g_Arh : g_Afh;
    const __half* inT  = hop ? (dir ? g_h1rT : g_h1fT) : g_hTh;
    __half* outR = hop ? (dir ? g_h2r : g_h2f) : (dir ? g_h1rR : g_h1fR);
    __half* outT = dir ? g_h1rT : g_h1fT;

    const int bt = blockIdx.y, n0 = blockIdx.x * 256;
    const int tid = threadIdx.x, w = tid >> 5, lane = tid & 31;
    const int grp = lane >> 2, q = lane & 3;
    const int wM = w & 3, wN = w >> 2;
    const uint32_t lA = laneA_off(wM * 64, lane);
    const uint32_t lB = laneB_off(wN * 32, lane);

    float acc[4][4][4];
#pragma unroll
    for (int a = 0; a < 4; ++a)
#pragma unroll
        for (int b = 0; b < 4; ++b)
#pragma unroll
            for (int c = 0; c < 4; ++c) acc[a][b][c] = 0.f;

#define HOP_ISSUE(kc, buf) {                                                    \
        _Pragma("unroll")                                                       \
        for (int i = 0; i < 8; ++i) {                                           \
            int li = tid + i * 256, row = li >> 3, seg = li & 7;                \
            cpa16(sA + ((buf) * HOPA_BUF + row * RS + seg * 8) * 2,             \
                  Aadj + (size_t)(n0 + row) * NNODE + (kc) * 64 + seg * 8);     \
        }                                                                       \
        _Pragma("unroll")                                                       \
        for (int i = 0; i < 2; ++i) {                                           \
            int li = tid + i * 256, row = li >> 3, seg = li & 7;                \
            cpa16(sB + ((buf) * HOPB_BUF + row * RS + seg * 8) * 2,             \
                  inT + ((size_t)bt * CC + row) * NNODE + (kc) * 64 + seg * 8); \
        }                                                                       \
        cp_commit();                                                            \
    }

    HOP_ISSUE(0, 0);
    for (int kc = 0; kc < 8; ++kc) {
        if (kc + 1 < 8) { HOP_ISSUE(kc + 1, (kc + 1) & 1); cp_wait<1>(); }
        else cp_wait<0>();
        __syncthreads();
        MMA_CHUNK(sA + (kc & 1) * HOPA_BUF * 2 + lA,
                  sB + (kc & 1) * HOPB_BUF * 2 + lB);
        __syncthreads();
    }

    // stage raw acc (rounded) into S[n 256][RS]
    __half* S = As;
#pragma unroll
    for (int mt = 0; mt < 4; ++mt)
#pragma unroll
        for (int hf = 0; hf < 2; ++hf) {
            int rl = wM * 64 + mt * 16 + grp + hf * 8;
#pragma unroll
            for (int nt = 0; nt < 4; ++nt) {
                int col = wN * 32 + nt * 8 + 2 * q;
                *reinterpret_cast<uint32_t*>(&S[rl * RS + col]) =
                    packh2(acc[mt][nt][hf * 2 + 0], acc[mt][nt][hf * 2 + 1]);
            }
        }
    __syncthreads();

    const float om = 1.f - ALPHA;
    // pass 1: outR [n][f], blended with g_hh (all coalesced 16B)
#pragma unroll
    for (int i = 0; i < 8; ++i) {
        int li = tid + i * 256, row = li >> 3, seg = li & 7;
        size_t ga = ((size_t)bt * NNODE + n0 + row) * CC + seg * 8;
        uint4 sa = *reinterpret_cast<uint4*>(&S[row * RS + seg * 8]);
        uint4 ha = *reinterpret_cast<const uint4*>(g_hh + ga);
        uint4 o;
        uint32_t* sp = &sa.x; uint32_t* hp = &ha.x; uint32_t* op = &o.x;
#pragma unroll
        for (int k = 0; k < 4; ++k) {
            float2 av = unph2(sp[k]), hv = unph2(hp[k]);
            op[k] = packh2(ALPHA * hv.x + om * av.x, ALPHA * hv.y + om * av.y);
        }
        *reinterpret_cast<uint4*>(outR + ga) = o;
    }
    // pass 2 (hop0 only): outT [f][n], blended with g_hTh
    if (hop == 0) {
#pragma unroll
        for (int i = 0; i < 32; ++i) {
            int li = tid + i * 256, f = li >> 7, np = li & 127;
            size_t ga = ((size_t)bt * CC + f) * NNODE + n0 + 2 * np;
            float a0 = __half2float(S[(2 * np) * RS + f]);
            float a1 = __half2float(S[(2 * np + 1) * RS + f]);
            float2 hv = unph2(*reinterpret_cast<const uint32_t*>(g_hTh + ga));
            *reinterpret_cast<uint32_t*>(outT + ga) =
                packh2(ALPHA * hv.x + om * a0, ALPHA * hv.y + om * a1);
        }
    }
}

// =============================================================================
// final: CTA 128 rows x 128 cols (64 out + 64 skip), K=320 in 5 chunks of 64
// =============================================================================
__global__ __launch_bounds__(256, 2) void final_fp16(const float* __restrict__ x,
                                                     float* __restrict__ out) {
    extern __shared__ __align__(16) __half smemh[];
    __half* As = smemh;                  // 2 x [128][RS]
    __half* Bs = smemh + 2 * CONV_BUF;
    const uint32_t sA = s2u(As), sB = s2u(Bs);
    const int r0 = blockIdx.x * 128;
    const int tid = threadIdx.x, w = tid >> 5, lane = tid & 31;
    const int grp = lane >> 2, q = lane & 3;
    const int wM = w & 1, wN = w >> 1;
    const uint32_t lA = laneA_off(wM * 64, lane);
    const uint32_t lB = laneB_off(wN * 32, lane);

    float acc[4][4][4];
#pragma unroll
    for (int a = 0; a < 4; ++a)
#pragma unroll
        for (int b = 0; b < 4; ++b)
#pragma unroll
            for (int c = 0; c < 4; ++c) acc[a][b][c] = 0.f;

    const __half* const srcs[5] = {g_hh, g_h1fR, g_h2f, g_h1rR, g_h2r};

#define FIN_ISSUE(kc, buf) {                                                    \
        const __half* sp = srcs[kc];                                            \
        _Pragma("unroll")                                                       \
        for (int i = 0; i < 4; ++i) {                                           \
            int li = tid + i * 256, row = li >> 3, seg = li & 7;                \
            cpa16(sA + ((buf) * CONV_BUF + row * RS + seg * 8) * 2,             \
                  sp + (size_t)(r0 + row) * CC + seg * 8);                      \
            cpa16(sB + ((buf) * CONV_BUF + row * RS + seg * 8) * 2,             \
                  g_WfinTh + row * 320 + (kc) * 64 + seg * 8);                  \
        }                                                                       \
        cp_commit();                                                            \
    }

    FIN_ISSUE(0, 0);
    for (int kc = 0; kc < 5; ++kc) {
        if (kc + 1 < 5) { FIN_ISSUE(kc + 1, (kc + 1) & 1); cp_wait<1>(); }
        else cp_wait<0>();
        __syncthreads();
        MMA_CHUNK(sA + (kc & 1) * CONV_BUF * 2 + lA,
                  sB + (kc & 1) * CONV_BUF * 2 + lB);
        __syncthreads();
    }

#pragma unroll
    for (int mt = 0; mt < 4; ++mt)
#pragma unroll
        for (int hf = 0; hf < 2; ++hf) {
            int row = r0 + wM * 64 + mt * 16 + grp + hf * 8;
#pragma unroll
            for (int nt = 0; nt < 4; ++nt) {
                int col = wN * 32 + nt * 8 + 2 * q;
                float d0 = acc[mt][nt][hf * 2 + 0] + g_bfin[col];
                float d1 = acc[mt][nt][hf * 2 + 1] + g_bfin[col + 1];
                if (wN < 2) {   // out half: + residual x
                    size_t a = (size_t)row * CC + col;
                    float2 xr = *reinterpret_cast<const float2*>(&x[a]);
                    *reinterpret_cast<float2*>(&out[a]) = make_float2(d0 + xr.x, d1 + xr.y);
                } else {        // skip half
                    size_t a = HN + (size_t)row * CC + (col - 64);
                    *reinterpret_cast<float2*>(&out[a]) = make_float2(d0, d1);
                }
            }
        }
}

// ---------------- launch ------------------------------------------------------
extern "C" void kernel_launch(void* const* d_in, const int* in_sizes, int n_in,
                              void* d_out, int out_size) {
    P p;
    p.x   = (const float*)d_in[0];
    p.adj = (const float*)d_in[1];
    for (int b = 0; b < 4; ++b) {
        p.wf[b] = (const float*)d_in[2 + b * 4 + 0];
        p.bf[b] = (const float*)d_in[2 + b * 4 + 1];
        p.wg[b] = (const float*)d_in[2 + b * 4 + 2];
        p.bg[b] = (const float*)d_in[2 + b * 4 + 3];
    }
    p.Wgf = (const float*)d_in[18];
    p.bgf = (const float*)d_in[19];
    p.Wgr = (const float*)d_in[20];
    p.bgr = (const float*)d_in[21];
    p.Ws  = (const float*)d_in[22];
    p.bs  = (const float*)d_in[23];
    float* out = (float*)d_out;

    const int smemCF = 4 * CONV_BUF * 2;                   // 73728 B
    const int smemH  = (2 * HOPA_BUF + 2 * HOPB_BUF) * 2;  // 92160 B
    cudaFuncSetAttribute(conv_fp16,  cudaFuncAttributeMaxDynamicSharedMemorySize, smemCF);
    cudaFuncSetAttribute(final_fp16, cudaFuncAttributeMaxDynamicSharedMemorySize, smemCF);
    cudaFuncSetAttribute(hop_fp16,   cudaFuncAttributeMaxDynamicSharedMemorySize, smemH);

    prep_adj<<<NNODE, 256>>>(p.adj);
    prep_w<<<385, 256>>>(p);
    prep_xh<<<HN / 8 / 256, 256>>>(p.x);

    dim3 gc(4, BT);
    conv_fp16<<<gc, 256, smemCF>>>();

    dim3 gh(2, BT, 2);
    hop_fp16<<<gh, 256, smemH>>>(0);
    hop_fp16<<<gh, 256, smemH>>>(1);

    final_fp16<<<BTN / 128, 256, smemCF>>>(p.x, out);
}